// round 10
// baseline (speedup 1.0000x reference)
#include <cuda_runtime.h>

#define Bb 8
#define Tt 2048
#define SH 36      // S*H
#define CH 48      // channels in x
#define LDIM 512
#define WTOT 18
#define TTILE 128

// -------- scratch (device globals: no allocation allowed) ----------
__device__ float g_part[Bb * 16 * CH];
__device__ float g_coef[4 * Bb * Tt * 12];   // [i][b][t][12]: a0..a8, mw, pad, pad

// -------- helpers ----------
__device__ __forceinline__ int refl(int t) {
    t = t < 0 ? -t : t;
    return t >= Tt ? (2 * Tt - 2 - t) : t;
}

__device__ __forceinline__ unsigned long long pk2(float a, float b) {
    unsigned long long r;
    asm("mov.b64 %0, {%1, %2};" : "=l"(r) : "f"(a), "f"(b));
    return r;
}
__device__ __forceinline__ void upk2(unsigned long long p, float& a, float& b) {
    asm("mov.b64 {%0, %1}, %2;" : "=f"(a), "=f"(b) : "l"(p));
}
// packed dual-fp32 FMA (sm_100+ PTX)
__device__ __forceinline__ void ffma2(unsigned long long& d,
                                      unsigned long long a, unsigned long long b) {
    asm("fma.rn.f32x2 %0, %1, %2, %0;" : "+l"(d) : "l"(a), "l"(b));
}

// -------- stats phase 1: partial channel sums, 16 partials per batch ----------
__global__ void __launch_bounds__(192) k_stats1(const float* __restrict__ x) {
    const int bx = blockIdx.x;          // b*16 + part
    const int b = bx >> 4;
    const int part = bx & 15;
    const int c = threadIdx.x % CH;
    const int y = threadIdx.x / CH;     // 0..3
    float s = 0.f;
    const float* base = x + ((size_t)b * Tt + part * 128) * CH + c;
#pragma unroll 4
    for (int r = 0; r < 32; r++)
        s += base[(size_t)(y + r * 4) * CH];
    __shared__ float sh[4][CH];
    sh[y][c] = s;
    __syncthreads();
    if (y == 0)
        g_part[bx * CH + c] = sh[0][c] + sh[1][c] + sh[2][c] + sh[3][c];
}

// -------- K2: per-(i,b,t) blur coefficients (weights derived in-block) ----------
__global__ void __launch_bounds__(256) k_coef(const float* __restrict__ x) {
    const int idx = blockIdx.x * 256 + threadIdx.x;   // i*B*T + b*T + t
    const int t = idx % Tt;
    const int bi = idx / Tt;
    const int b = bi % Bb;
    const int i = bi / Bb;

    __shared__ float ws[9];
    if (threadIdx.x == 0) {
        float tot = 0.f;
#pragma unroll
        for (int p = 0; p < 16; p++)
            tot += g_part[(b * 16 + p) * CH + SH + 3 * i + 2];
        float sig = fmaxf(tot * (1.0f / Tt), 0.001f);
        float inv2 = 1.0f / (sig * sig);
        float w[9];
        float wsum = 0.f;
#pragma unroll
        for (int j = 0; j < 9; j++) {
            float k = (float)(j - 4);
            w[j] = expf(-0.5f * k * k * inv2);
            wsum += w[j];
        }
        float inv = 1.0f / wsum;
#pragma unroll
        for (int j = 0; j < 9; j++)
            ws[j] = w[j] * inv;
    }
    __syncthreads();

    float mw = 0.f;
    float o[12];
#pragma unroll
    for (int j = 0; j < 9; j++) {
        int tj = refl(t - 4 + j);
        const float* row = x + ((size_t)b * Tt + tj) * CH + SH + 3 * i;
        float mu = row[0], sg = row[1];
        o[j] = ws[j] * sg;
        mw = fmaf(ws[j], mu, mw);
    }
    o[9] = mw; o[10] = 0.f; o[11] = 0.f;
    float4* dst = (float4*)(g_coef + (size_t)idx * 12);
    dst[0] = make_float4(o[0], o[1], o[2], o[3]);
    dst[1] = make_float4(o[4], o[5], o[6], o[7]);
    dst[2] = make_float4(o[8], o[9], o[10], o[11]);
}

// -------- lats block body: lats = (env - mean) @ lat ----------
// env stored transposed [h][t] in smem; 2 t-values per inner iteration.
__device__ __forceinline__ void lats_blk(const float* __restrict__ x,
                                         const float* __restrict__ lt,
                                         float* __restrict__ out,
                                         int id, int tid) {
    const int w = id % WTOT;
    const int bt = id / WTOT;
    const int b = bt / (Tt / TTILE);
    const int t0 = (bt % (Tt / TTILE)) * TTILE;
    const int i = w / 6;
    const int l4 = tid * 4;

    unsigned long long lp[12][2];
#pragma unroll
    for (int h = 0; h < 12; h++) {
        const float4 v = *(const float4*)(lt + ((size_t)(i * 12 + h) * WTOT + w) * LDIM + l4);
        lp[h][0] = pk2(v.x, v.y);
        lp[h][1] = pk2(v.z, v.w);
    }

    __shared__ float env[12 * TTILE];
    __shared__ float mean[12];
    if (tid < 12) {
        float tot = 0.f;
#pragma unroll
        for (int p = 0; p < 16; p++)
            tot += g_part[(b * 16 + p) * CH + i * 12 + tid];
        mean[tid] = tot * (1.0f / Tt);
    }
    __syncthreads();
    for (int idx = tid; idx < TTILE * 12; idx += 128) {
        int tl = idx / 12, h = idx % 12;
        env[h * TTILE + tl] = x[((size_t)b * Tt + t0 + tl) * CH + i * 12 + h] - mean[h];
    }
    __syncthreads();

    float* ob = out + (((size_t)b * Tt + t0) * WTOT + w) * LDIM + l4;
    for (int tl = 0; tl < TTILE; tl += 2) {
        unsigned long long a0 = 0ULL, a1 = 0ULL, a2 = 0ULL, a3 = 0ULL;
#pragma unroll
        for (int h = 0; h < 12; h++) {
            const float2 e = *(const float2*)&env[h * TTILE + tl];
            unsigned long long ep0 = pk2(e.x, e.x);
            unsigned long long ep1 = pk2(e.y, e.y);
            ffma2(a0, lp[h][0], ep0);
            ffma2(a1, lp[h][1], ep0);
            ffma2(a2, lp[h][0], ep1);
            ffma2(a3, lp[h][1], ep1);
        }
        float4 r0, r1;
        upk2(a0, r0.x, r0.y);
        upk2(a1, r0.z, r0.w);
        upk2(a2, r1.x, r1.y);
        upk2(a3, r1.z, r1.w);
        *(float4*)(ob + (size_t)tl * (WTOT * LDIM)) = r0;
        *(float4*)(ob + (size_t)(tl + 1) * (WTOT * LDIM)) = r1;
    }
}

// -------- noise block body: rolling 9-tap eps window in registers ----------
template <int QUADS, int QB, int TBLK>
__device__ __forceinline__ void noise_blk(const float4* __restrict__ eps,
                                          float4* __restrict__ out,
                                          int ni, int idx, int tid) {
    constexpr int ROWS = 128 / QB;
    constexpr int TILES = Tt / (ROWS * TBLK);
    constexpr int NSPLIT = QUADS / QB;
    constexpr int PERB = TILES * NSPLIT;

    const int b = idx / PERB;
    const int rem = idx % PERB;
    const int split = rem % NSPLIT;
    const int tile = rem / NSPLIT;
    const int q = split * QB + (tid % QB);
    const int row = tid / QB;
    const int t0 = tile * ROWS * TBLK + row * TBLK;

    const float4* ep = eps + (size_t)b * Tt * QUADS;
    const float4* cf = (const float4*)g_coef + ((size_t)(ni * Bb + b) * Tt) * 3;
    float4* ob = out + (size_t)b * Tt * QUADS + q;

    // window: wnd[j] = eps[refl(t-4+j)]
    ulonglong2 wnd[9];
#pragma unroll
    for (int j = 0; j < 8; j++)
        wnd[j] = *(const ulonglong2*)(ep + (size_t)refl(t0 - 4 + j) * QUADS + q);

#pragma unroll 4
    for (int t = t0; t < t0 + TBLK; t++) {
        wnd[8] = *(const ulonglong2*)(ep + (size_t)refl(t + 4) * QUADS + q);

        float4 c0 = cf[t * 3 + 0];
        float4 c1 = cf[t * 3 + 1];
        float4 c2 = cf[t * 3 + 2];
        const float a[9] = {c0.x, c0.y, c0.z, c0.w, c1.x, c1.y, c1.z, c1.w, c2.x};
        unsigned long long s0 = pk2(c2.y, c2.y);
        unsigned long long s1 = s0;
#pragma unroll
        for (int j = 0; j < 9; j++) {
            unsigned long long ap = pk2(a[j], a[j]);
            ffma2(s0, wnd[j].x, ap);
            ffma2(s1, wnd[j].y, ap);
        }
        float4 r;
        upk2(s0, r.x, r.y);
        upk2(s1, r.z, r.w);
        ob[(size_t)t * QUADS] = r;

#pragma unroll
        for (int j = 0; j < 8; j++) wnd[j] = wnd[j + 1];
    }
}

// -------- mega kernel: lats + all noise, one launch ----------
#define NB_L  (Bb * (Tt / TTILE) * WTOT)   // 2304
#define NB_0  128                          // <4,4,4>    : 8 * 16
#define NB_1  128                          // <16,16,16> : 8 * 16
#define NB_2  256                          // <64,64,32> : 8 * 32
#define NB_3  1024                         // <256,128,32>: 8 * 128

__global__ void __launch_bounds__(128) k_mega(const float* __restrict__ x,
                                              const float* __restrict__ lt,
                                              const float4* __restrict__ e0,
                                              const float4* __restrict__ e1,
                                              const float4* __restrict__ e2,
                                              const float4* __restrict__ e3,
                                              float* __restrict__ out) {
    const size_t OFF0 = (size_t)Bb * Tt * WTOT * LDIM;
    const size_t OFF1 = OFF0 + (size_t)Bb * Tt * 16;
    const size_t OFF2 = OFF1 + (size_t)Bb * Tt * 64;
    const size_t OFF3 = OFF2 + (size_t)Bb * Tt * 256;

    const int bx = blockIdx.x;
    const int tid = threadIdx.x;

    if (bx < NB_L) {
        lats_blk(x, lt, out, bx, tid);
    } else if (bx < NB_L + NB_0) {
        noise_blk<4, 4, 4>(e0, (float4*)(out + OFF0), 0, bx - NB_L, tid);
    } else if (bx < NB_L + NB_0 + NB_1) {
        noise_blk<16, 16, 16>(e1, (float4*)(out + OFF1), 1, bx - NB_L - NB_0, tid);
    } else if (bx < NB_L + NB_0 + NB_1 + NB_2) {
        noise_blk<64, 64, 32>(e2, (float4*)(out + OFF2), 2, bx - NB_L - NB_0 - NB_1, tid);
    } else {
        noise_blk<256, 128, 32>(e3, (float4*)(out + OFF3), 3,
                                bx - NB_L - NB_0 - NB_1 - NB_2, tid);
    }
}

// -------- launch ----------
extern "C" void kernel_launch(void* const* d_in, const int* in_sizes, int n_in,
                              void* d_out, int out_size) {
    const float* x  = (const float*)d_in[0];
    const float* lt = (const float*)d_in[1];
    const float4* e0 = (const float4*)d_in[2];
    const float4* e1 = (const float4*)d_in[3];
    const float4* e2 = (const float4*)d_in[4];
    const float4* e3 = (const float4*)d_in[5];
    float* out = (float*)d_out;

    k_stats1<<<Bb * 16, 192>>>(x);
    k_coef<<<4 * Bb * Tt / 256, 256>>>(x);
    k_mega<<<NB_L + NB_0 + NB_1 + NB_2 + NB_3, 128>>>(x, lt, e0, e1, e2, e3, out);
}

// round 11
// speedup vs baseline: 1.3195x; 1.3195x over previous
#include <cuda_runtime.h>

#define Bb 8
#define Tt 2048
#define SH 36      // S*H
#define CH 48      // channels in x
#define LDIM 512
#define WTOT 18
#define TTILE 128

// -------- scratch (device globals: no allocation allowed) ----------
__device__ float g_part[Bb * 16 * CH];
__device__ float g_coef[4 * Bb * Tt * 12];   // [i][b][t][12]: a0..a8, mw, pad, pad

// -------- helpers ----------
__device__ __forceinline__ int refl(int t) {
    t = t < 0 ? -t : t;
    return t >= Tt ? (2 * Tt - 2 - t) : t;
}

__device__ __forceinline__ unsigned long long pk2(float a, float b) {
    unsigned long long r;
    asm("mov.b64 %0, {%1, %2};" : "=l"(r) : "f"(a), "f"(b));
    return r;
}
__device__ __forceinline__ void upk2(unsigned long long p, float& a, float& b) {
    asm("mov.b64 {%0, %1}, %2;" : "=f"(a), "=f"(b) : "l"(p));
}
// packed dual-fp32 FMA (sm_100+ PTX)
__device__ __forceinline__ void ffma2(unsigned long long& d,
                                      unsigned long long a, unsigned long long b) {
    asm("fma.rn.f32x2 %0, %1, %2, %0;" : "+l"(d) : "l"(a), "l"(b));
}

// -------- stats phase 1: partial channel sums, 16 partials per batch ----------
__global__ void __launch_bounds__(192) k_stats1(const float* __restrict__ x) {
    const int bx = blockIdx.x;          // b*16 + part
    const int b = bx >> 4;
    const int part = bx & 15;
    const int c = threadIdx.x % CH;
    const int y = threadIdx.x / CH;     // 0..3
    float s = 0.f;
    const float* base = x + ((size_t)b * Tt + part * 128) * CH + c;
#pragma unroll 4
    for (int r = 0; r < 32; r++)
        s += base[(size_t)(y + r * 4) * CH];
    __shared__ float sh[4][CH];
    sh[y][c] = s;
    __syncthreads();
    if (y == 0)
        g_part[bx * CH + c] = sh[0][c] + sh[1][c] + sh[2][c] + sh[3][c];
}

// -------- K2: per-(i,b,t) blur coefficients (weights derived in-block) ----------
__global__ void __launch_bounds__(256) k_coef(const float* __restrict__ x) {
    const int idx = blockIdx.x * 256 + threadIdx.x;   // i*B*T + b*T + t
    const int t = idx % Tt;
    const int bi = idx / Tt;
    const int b = bi % Bb;
    const int i = bi / Bb;

    __shared__ float ws[9];
    if (threadIdx.x == 0) {
        float tot = 0.f;
#pragma unroll
        for (int p = 0; p < 16; p++)
            tot += g_part[(b * 16 + p) * CH + SH + 3 * i + 2];
        float sig = fmaxf(tot * (1.0f / Tt), 0.001f);
        float inv2 = 1.0f / (sig * sig);
        float w[9];
        float wsum = 0.f;
#pragma unroll
        for (int j = 0; j < 9; j++) {
            float k = (float)(j - 4);
            w[j] = expf(-0.5f * k * k * inv2);
            wsum += w[j];
        }
        float inv = 1.0f / wsum;
#pragma unroll
        for (int j = 0; j < 9; j++)
            ws[j] = w[j] * inv;
    }
    __syncthreads();

    float mw = 0.f;
    float o[12];
#pragma unroll
    for (int j = 0; j < 9; j++) {
        int tj = refl(t - 4 + j);
        const float* row = x + ((size_t)b * Tt + tj) * CH + SH + 3 * i;
        float mu = row[0], sg = row[1];
        o[j] = ws[j] * sg;
        mw = fmaf(ws[j], mu, mw);
    }
    o[9] = mw; o[10] = 0.f; o[11] = 0.f;
    float4* dst = (float4*)(g_coef + (size_t)idx * 12);
    dst[0] = make_float4(o[0], o[1], o[2], o[3]);
    dst[1] = make_float4(o[4], o[5], o[6], o[7]);
    dst[2] = make_float4(o[8], o[9], o[10], o[11]);
}

// -------- lats block body: lats = (env - mean) @ lat ----------
// R9 layout [tl][12]; reads paired over h via LDS.64 (broadcast, conflict-free).
__device__ __forceinline__ void lats_blk(const float* __restrict__ x,
                                         const float* __restrict__ lt,
                                         float* __restrict__ out,
                                         int id, int tid) {
    const int w = id % WTOT;
    const int bt = id / WTOT;
    const int b = bt / (Tt / TTILE);
    const int t0 = (bt % (Tt / TTILE)) * TTILE;
    const int i = w / 6;
    const int l4 = tid * 4;

    unsigned long long lp[12][2];
#pragma unroll
    for (int h = 0; h < 12; h++) {
        const float4 v = *(const float4*)(lt + ((size_t)(i * 12 + h) * WTOT + w) * LDIM + l4);
        lp[h][0] = pk2(v.x, v.y);
        lp[h][1] = pk2(v.z, v.w);
    }

    __shared__ float env[TTILE * 12];
    __shared__ float mean[12];
    if (tid < 12) {
        float tot = 0.f;
#pragma unroll
        for (int p = 0; p < 16; p++)
            tot += g_part[(b * 16 + p) * CH + i * 12 + tid];
        mean[tid] = tot * (1.0f / Tt);
    }
    __syncthreads();
    for (int idx = tid; idx < TTILE * 12; idx += 128) {
        int tl = idx / 12, h = idx % 12;
        env[idx] = x[((size_t)b * Tt + t0 + tl) * CH + i * 12 + h] - mean[h];
    }
    __syncthreads();

    float* ob = out + (((size_t)b * Tt + t0) * WTOT + w) * LDIM + l4;
    for (int tl = 0; tl < TTILE; tl++) {
        unsigned long long a0 = 0ULL, a1 = 0ULL;
#pragma unroll
        for (int h = 0; h < 12; h += 2) {
            const float2 e = *(const float2*)&env[tl * 12 + h];
            unsigned long long ep0 = pk2(e.x, e.x);
            unsigned long long ep1 = pk2(e.y, e.y);
            ffma2(a0, lp[h][0], ep0);
            ffma2(a1, lp[h][1], ep0);
            ffma2(a0, lp[h + 1][0], ep1);
            ffma2(a1, lp[h + 1][1], ep1);
        }
        float4 r;
        upk2(a0, r.x, r.y);
        upk2(a1, r.z, r.w);
        *(float4*)(ob + (size_t)tl * (WTOT * LDIM)) = r;
    }
}

// -------- noise block body: 2-t pairing, 10 transient taps per pair ----------
template <int QUADS, int QB, int TBLK>
__device__ __forceinline__ void noise_blk(const float4* __restrict__ eps,
                                          float4* __restrict__ out,
                                          int ni, int idx, int tid) {
    constexpr int ROWS = 128 / QB;
    constexpr int TILES = Tt / (ROWS * TBLK);
    constexpr int NSPLIT = QUADS / QB;
    constexpr int PERB = TILES * NSPLIT;

    const int b = idx / PERB;
    const int rem = idx % PERB;
    const int split = rem % NSPLIT;
    const int tile = rem / NSPLIT;
    const int q = split * QB + (tid % QB);
    const int row = tid / QB;
    const int t0 = tile * ROWS * TBLK + row * TBLK;

    const float4* ep = eps + (size_t)b * Tt * QUADS;
    const float4* cf = (const float4*)g_coef + ((size_t)(ni * Bb + b) * Tt) * 3;
    float4* ob = out + (size_t)b * Tt * QUADS + q;

    for (int t = t0; t < t0 + TBLK; t += 2) {
        // taps t-4 .. t+5 cover outputs t and t+1
        ulonglong2 tap[10];
        if (t >= 4 && t + 5 < Tt) {
#pragma unroll
            for (int j = 0; j < 10; j++)
                tap[j] = *(const ulonglong2*)(ep + (size_t)(t - 4 + j) * QUADS + q);
        } else {
#pragma unroll
            for (int j = 0; j < 10; j++)
                tap[j] = *(const ulonglong2*)(ep + (size_t)refl(t - 4 + j) * QUADS + q);
        }

        float4 c0 = cf[t * 3 + 0];
        float4 c1 = cf[t * 3 + 1];
        float4 c2 = cf[t * 3 + 2];
        float4 d0 = cf[t * 3 + 3];
        float4 d1 = cf[t * 3 + 4];
        float4 d2 = cf[t * 3 + 5];
        const float a[9] = {c0.x, c0.y, c0.z, c0.w, c1.x, c1.y, c1.z, c1.w, c2.x};
        const float g[9] = {d0.x, d0.y, d0.z, d0.w, d1.x, d1.y, d1.z, d1.w, d2.x};

        unsigned long long s0 = pk2(c2.y, c2.y);
        unsigned long long s1 = s0;
        unsigned long long u0 = pk2(d2.y, d2.y);
        unsigned long long u1 = u0;
#pragma unroll
        for (int j = 0; j < 9; j++) {
            unsigned long long ap = pk2(a[j], a[j]);
            unsigned long long gp = pk2(g[j], g[j]);
            ffma2(s0, tap[j].x, ap);
            ffma2(s1, tap[j].y, ap);
            ffma2(u0, tap[j + 1].x, gp);
            ffma2(u1, tap[j + 1].y, gp);
        }
        float4 r0, r1;
        upk2(s0, r0.x, r0.y);
        upk2(s1, r0.z, r0.w);
        upk2(u0, r1.x, r1.y);
        upk2(u1, r1.z, r1.w);
        ob[(size_t)t * QUADS] = r0;
        ob[(size_t)(t + 1) * QUADS] = r1;
    }
}

// -------- mega kernel: lats + all noise, one launch ----------
#define NB_L  (Bb * (Tt / TTILE) * WTOT)   // 2304
#define NB_0  128                          // <4,4,4>    : 8 * 16
#define NB_1  128                          // <16,16,16> : 8 * 16
#define NB_2  256                          // <64,64,32> : 8 * 32
#define NB_3  1024                         // <256,128,32>: 8 * 128

__global__ void __launch_bounds__(128) k_mega(const float* __restrict__ x,
                                              const float* __restrict__ lt,
                                              const float4* __restrict__ e0,
                                              const float4* __restrict__ e1,
                                              const float4* __restrict__ e2,
                                              const float4* __restrict__ e3,
                                              float* __restrict__ out) {
    const size_t OFF0 = (size_t)Bb * Tt * WTOT * LDIM;
    const size_t OFF1 = OFF0 + (size_t)Bb * Tt * 16;
    const size_t OFF2 = OFF1 + (size_t)Bb * Tt * 64;
    const size_t OFF3 = OFF2 + (size_t)Bb * Tt * 256;

    const int bx = blockIdx.x;
    const int tid = threadIdx.x;

    if (bx < NB_L) {
        lats_blk(x, lt, out, bx, tid);
    } else if (bx < NB_L + NB_0) {
        noise_blk<4, 4, 4>(e0, (float4*)(out + OFF0), 0, bx - NB_L, tid);
    } else if (bx < NB_L + NB_0 + NB_1) {
        noise_blk<16, 16, 16>(e1, (float4*)(out + OFF1), 1, bx - NB_L - NB_0, tid);
    } else if (bx < NB_L + NB_0 + NB_1 + NB_2) {
        noise_blk<64, 64, 32>(e2, (float4*)(out + OFF2), 2, bx - NB_L - NB_0 - NB_1, tid);
    } else {
        noise_blk<256, 128, 32>(e3, (float4*)(out + OFF3), 3,
                                bx - NB_L - NB_0 - NB_1 - NB_2, tid);
    }
}

// -------- launch ----------
extern "C" void kernel_launch(void* const* d_in, const int* in_sizes, int n_in,
                              void* d_out, int out_size) {
    const float* x  = (const float*)d_in[0];
    const float* lt = (const float*)d_in[1];
    const float4* e0 = (const float4*)d_in[2];
    const float4* e1 = (const float4*)d_in[3];
    const float4* e2 = (const float4*)d_in[4];
    const float4* e3 = (const float4*)d_in[5];
    float* out = (float*)d_out;

    k_stats1<<<Bb * 16, 192>>>(x);
    k_coef<<<4 * Bb * Tt / 256, 256>>>(x);
    k_mega<<<NB_L + NB_0 + NB_1 + NB_2 + NB_3, 128>>>(x, lt, e0, e1, e2, e3, out);
}

// round 12
// speedup vs baseline: 1.3504x; 1.0234x over previous
#include <cuda_runtime.h>

#define Bb 8
#define Tt 2048
#define SH 36      // S*H
#define CH 48      // channels in x
#define LDIM 512
#define WTOT 18
#define TTILE 128
#define NPART 32   // partials per batch

// -------- scratch (device globals: no allocation allowed) ----------
__device__ float g_part[Bb * NPART * CH];
__device__ float g_coef[4 * Bb * Tt * 12];   // [i][b][t][12]: a0..a8, mw, pad, pad

// -------- helpers ----------
__device__ __forceinline__ int refl(int t) {
    t = t < 0 ? -t : t;
    return t >= Tt ? (2 * Tt - 2 - t) : t;
}

__device__ __forceinline__ unsigned long long pk2(float a, float b) {
    unsigned long long r;
    asm("mov.b64 %0, {%1, %2};" : "=l"(r) : "f"(a), "f"(b));
    return r;
}
__device__ __forceinline__ void upk2(unsigned long long p, float& a, float& b) {
    asm("mov.b64 {%0, %1}, %2;" : "=f"(a), "=f"(b) : "l"(p));
}
// packed dual-fp32 FMA (sm_100+ PTX)
__device__ __forceinline__ void ffma2(unsigned long long& d,
                                      unsigned long long a, unsigned long long b) {
    asm("fma.rn.f32x2 %0, %1, %2, %0;" : "+l"(d) : "l"(a), "l"(b));
}

// -------- stats phase 1: vectorized partial channel sums ----------
// grid = Bb*NPART; block = 192 = 12 quads x 16 rows; LDG.128 coalesced.
__global__ void __launch_bounds__(192) k_stats1(const float4* __restrict__ x4) {
    const int bx = blockIdx.x;              // b*NPART + part
    const int b = bx / NPART;
    const int part = bx % NPART;
    const int q = threadIdx.x % 12;         // quad of channels (CH/4 = 12)
    const int y = threadIdx.x / 12;         // 0..15
    const int t0 = part * (Tt / NPART);     // 64 rows per part

    float4 s = make_float4(0.f, 0.f, 0.f, 0.f);
#pragma unroll
    for (int r = 0; r < 4; r++) {
        const float4 v = x4[((size_t)b * Tt + t0 + y + r * 16) * 12 + q];
        s.x += v.x; s.y += v.y; s.z += v.z; s.w += v.w;
    }
    __shared__ float4 sh[16][12];
    sh[y][q] = s;
    __syncthreads();
    if (y == 0) {
        float4 tot = sh[0][q];
#pragma unroll
        for (int yy = 1; yy < 16; yy++) {
            const float4 v = sh[yy][q];
            tot.x += v.x; tot.y += v.y; tot.z += v.z; tot.w += v.w;
        }
        *(float4*)(&g_part[(size_t)bx * CH + q * 4]) = tot;
    }
}

// -------- K2: per-(i,b,t) blur coefficients (weights derived in-block) ----------
__global__ void __launch_bounds__(256) k_coef(const float* __restrict__ x) {
    const int idx = blockIdx.x * 256 + threadIdx.x;   // i*B*T + b*T + t
    const int t = idx % Tt;
    const int bi = idx / Tt;
    const int b = bi % Bb;
    const int i = bi / Bb;

    __shared__ float ws[9];
    if (threadIdx.x == 0) {
        float tot = 0.f;
#pragma unroll
        for (int p = 0; p < NPART; p++)
            tot += g_part[(b * NPART + p) * CH + SH + 3 * i + 2];
        float sig = fmaxf(tot * (1.0f / Tt), 0.001f);
        float inv2 = 1.0f / (sig * sig);
        float w[9];
        float wsum = 0.f;
#pragma unroll
        for (int j = 0; j < 9; j++) {
            float k = (float)(j - 4);
            w[j] = expf(-0.5f * k * k * inv2);
            wsum += w[j];
        }
        float inv = 1.0f / wsum;
#pragma unroll
        for (int j = 0; j < 9; j++)
            ws[j] = w[j] * inv;
    }
    __syncthreads();

    float mw = 0.f;
    float o[12];
#pragma unroll
    for (int j = 0; j < 9; j++) {
        int tj = refl(t - 4 + j);
        const float* row = x + ((size_t)b * Tt + tj) * CH + SH + 3 * i;
        float mu = row[0], sg = row[1];
        o[j] = ws[j] * sg;
        mw = fmaf(ws[j], mu, mw);
    }
    o[9] = mw; o[10] = 0.f; o[11] = 0.f;
    float4* dst = (float4*)(g_coef + (size_t)idx * 12);
    dst[0] = make_float4(o[0], o[1], o[2], o[3]);
    dst[1] = make_float4(o[4], o[5], o[6], o[7]);
    dst[2] = make_float4(o[8], o[9], o[10], o[11]);
}

// -------- lats block body: lats = (env - mean) @ lat ----------
// [tl][12] smem layout; reads paired over h via LDS.64 (broadcast, conflict-free).
__device__ __forceinline__ void lats_blk(const float* __restrict__ x,
                                         const float* __restrict__ lt,
                                         float* __restrict__ out,
                                         int id, int tid) {
    const int w = id % WTOT;
    const int bt = id / WTOT;
    const int b = bt / (Tt / TTILE);
    const int t0 = (bt % (Tt / TTILE)) * TTILE;
    const int i = w / 6;
    const int l4 = tid * 4;

    unsigned long long lp[12][2];
#pragma unroll
    for (int h = 0; h < 12; h++) {
        const float4 v = *(const float4*)(lt + ((size_t)(i * 12 + h) * WTOT + w) * LDIM + l4);
        lp[h][0] = pk2(v.x, v.y);
        lp[h][1] = pk2(v.z, v.w);
    }

    __shared__ float env[TTILE * 12];
    __shared__ float mean[12];
    if (tid < 12) {
        float tot = 0.f;
#pragma unroll
        for (int p = 0; p < NPART; p++)
            tot += g_part[(b * NPART + p) * CH + i * 12 + tid];
        mean[tid] = tot * (1.0f / Tt);
    }
    __syncthreads();
    for (int idx = tid; idx < TTILE * 12; idx += 128) {
        int tl = idx / 12, h = idx % 12;
        env[idx] = x[((size_t)b * Tt + t0 + tl) * CH + i * 12 + h] - mean[h];
    }
    __syncthreads();

    float* ob = out + (((size_t)b * Tt + t0) * WTOT + w) * LDIM + l4;
    for (int tl = 0; tl < TTILE; tl++) {
        unsigned long long a0 = 0ULL, a1 = 0ULL;
#pragma unroll
        for (int h = 0; h < 12; h += 2) {
            const float2 e = *(const float2*)&env[tl * 12 + h];
            unsigned long long ep0 = pk2(e.x, e.x);
            unsigned long long ep1 = pk2(e.y, e.y);
            ffma2(a0, lp[h][0], ep0);
            ffma2(a1, lp[h][1], ep0);
            ffma2(a0, lp[h + 1][0], ep1);
            ffma2(a1, lp[h + 1][1], ep1);
        }
        float4 r;
        upk2(a0, r.x, r.y);
        upk2(a1, r.z, r.w);
        *(float4*)(ob + (size_t)tl * (WTOT * LDIM)) = r;
    }
}

// -------- noise block body: 2-t pairing, 10 transient taps per pair ----------
template <int QUADS, int QB, int TBLK>
__device__ __forceinline__ void noise_blk(const float4* __restrict__ eps,
                                          float4* __restrict__ out,
                                          int ni, int idx, int tid) {
    constexpr int ROWS = 128 / QB;
    constexpr int TILES = Tt / (ROWS * TBLK);
    constexpr int NSPLIT = QUADS / QB;
    constexpr int PERB = TILES * NSPLIT;

    const int b = idx / PERB;
    const int rem = idx % PERB;
    const int split = rem % NSPLIT;
    const int tile = rem / NSPLIT;
    const int q = split * QB + (tid % QB);
    const int row = tid / QB;
    const int t0 = tile * ROWS * TBLK + row * TBLK;

    const float4* ep = eps + (size_t)b * Tt * QUADS;
    const float4* cf = (const float4*)g_coef + ((size_t)(ni * Bb + b) * Tt) * 3;
    float4* ob = out + (size_t)b * Tt * QUADS + q;

    for (int t = t0; t < t0 + TBLK; t += 2) {
        // taps t-4 .. t+5 cover outputs t and t+1
        ulonglong2 tap[10];
        if (t >= 4 && t + 5 < Tt) {
#pragma unroll
            for (int j = 0; j < 10; j++)
                tap[j] = *(const ulonglong2*)(ep + (size_t)(t - 4 + j) * QUADS + q);
        } else {
#pragma unroll
            for (int j = 0; j < 10; j++)
                tap[j] = *(const ulonglong2*)(ep + (size_t)refl(t - 4 + j) * QUADS + q);
        }

        float4 c0 = cf[t * 3 + 0];
        float4 c1 = cf[t * 3 + 1];
        float4 c2 = cf[t * 3 + 2];
        float4 d0 = cf[t * 3 + 3];
        float4 d1 = cf[t * 3 + 4];
        float4 d2 = cf[t * 3 + 5];
        const float a[9] = {c0.x, c0.y, c0.z, c0.w, c1.x, c1.y, c1.z, c1.w, c2.x};
        const float g[9] = {d0.x, d0.y, d0.z, d0.w, d1.x, d1.y, d1.z, d1.w, d2.x};

        unsigned long long s0 = pk2(c2.y, c2.y);
        unsigned long long s1 = s0;
        unsigned long long u0 = pk2(d2.y, d2.y);
        unsigned long long u1 = u0;
#pragma unroll
        for (int j = 0; j < 9; j++) {
            unsigned long long ap = pk2(a[j], a[j]);
            unsigned long long gp = pk2(g[j], g[j]);
            ffma2(s0, tap[j].x, ap);
            ffma2(s1, tap[j].y, ap);
            ffma2(u0, tap[j + 1].x, gp);
            ffma2(u1, tap[j + 1].y, gp);
        }
        float4 r0, r1;
        upk2(s0, r0.x, r0.y);
        upk2(s1, r0.z, r0.w);
        upk2(u0, r1.x, r1.y);
        upk2(u1, r1.z, r1.w);
        ob[(size_t)t * QUADS] = r0;
        ob[(size_t)(t + 1) * QUADS] = r1;
    }
}

// -------- mega kernel: lats + all noise, one launch ----------
#define NB_L  (Bb * (Tt / TTILE) * WTOT)   // 2304
#define NB_0  128                          // <4,4,4>    : 8 * 16
#define NB_1  128                          // <16,16,16> : 8 * 16
#define NB_2  256                          // <64,64,32> : 8 * 32
#define NB_3  1024                         // <256,128,32>: 8 * 128

__global__ void __launch_bounds__(128) k_mega(const float* __restrict__ x,
                                              const float* __restrict__ lt,
                                              const float4* __restrict__ e0,
                                              const float4* __restrict__ e1,
                                              const float4* __restrict__ e2,
                                              const float4* __restrict__ e3,
                                              float* __restrict__ out) {
    const size_t OFF0 = (size_t)Bb * Tt * WTOT * LDIM;
    const size_t OFF1 = OFF0 + (size_t)Bb * Tt * 16;
    const size_t OFF2 = OFF1 + (size_t)Bb * Tt * 64;
    const size_t OFF3 = OFF2 + (size_t)Bb * Tt * 256;

    const int bx = blockIdx.x;
    const int tid = threadIdx.x;

    if (bx < NB_L) {
        lats_blk(x, lt, out, bx, tid);
    } else if (bx < NB_L + NB_0) {
        noise_blk<4, 4, 4>(e0, (float4*)(out + OFF0), 0, bx - NB_L, tid);
    } else if (bx < NB_L + NB_0 + NB_1) {
        noise_blk<16, 16, 16>(e1, (float4*)(out + OFF1), 1, bx - NB_L - NB_0, tid);
    } else if (bx < NB_L + NB_0 + NB_1 + NB_2) {
        noise_blk<64, 64, 32>(e2, (float4*)(out + OFF2), 2, bx - NB_L - NB_0 - NB_1, tid);
    } else {
        noise_blk<256, 128, 32>(e3, (float4*)(out + OFF3), 3,
                                bx - NB_L - NB_0 - NB_1 - NB_2, tid);
    }
}

// -------- launch ----------
extern "C" void kernel_launch(void* const* d_in, const int* in_sizes, int n_in,
                              void* d_out, int out_size) {
    const float* x  = (const float*)d_in[0];
    const float* lt = (const float*)d_in[1];
    const float4* e0 = (const float4*)d_in[2];
    const float4* e1 = (const float4*)d_in[3];
    const float4* e2 = (const float4*)d_in[4];
    const float4* e3 = (const float4*)d_in[5];
    float* out = (float*)d_out;

    k_stats1<<<Bb * NPART, 192>>>((const float4*)x);
    k_coef<<<4 * Bb * Tt / 256, 256>>>(x);
    k_mega<<<NB_L + NB_0 + NB_1 + NB_2 + NB_3, 128>>>(x, lt, e0, e1, e2, e3, out);
}